// round 17
// baseline (speedup 1.0000x reference)
#include <cuda_runtime.h>
#include <cuda_fp16.h>
#include <cstdint>

#define BN_TOT 2048
#define M_DIM  256
#define CIN    64
#define CMID   256
#define COUT   256
#define W2P    320
#define K2P    65
#define AP     72          // fp16 smem pitch (144B rows), verified round 4

// device scratch (zero-alloc rule)
__device__ float g_zmax[BN_TOT * CMID];   // 2 MB, final max(+bias)
__device__ float g_v[BN_TOT * COUT];      // 2 MB

// ---------------- PTX helpers ----------------
__device__ __forceinline__ unsigned smem_u32(const void* p) {
    return (unsigned)__cvta_generic_to_shared(p);
}
__device__ __forceinline__ void ldm4(unsigned r[4], unsigned addr) {
    asm volatile("ldmatrix.sync.aligned.m8n8.x4.shared.b16 {%0,%1,%2,%3}, [%4];"
                 : "=r"(r[0]), "=r"(r[1]), "=r"(r[2]), "=r"(r[3]) : "r"(addr));
}
__device__ __forceinline__ void mma_f16(float c[4], const unsigned a[4], const unsigned b[2]) {
    asm volatile("mma.sync.aligned.m16n8k16.row.col.f32.f16.f16.f32 "
                 "{%0,%1,%2,%3}, {%4,%5,%6,%7}, {%8,%9}, {%0,%1,%2,%3};"
                 : "+f"(c[0]), "+f"(c[1]), "+f"(c[2]), "+f"(c[3])
                 : "r"(a[0]), "r"(a[1]), "r"(a[2]), "r"(a[3]), "r"(b[0]), "r"(b[1]));
}

// ---------------------------------------------------------------------------
// Round-4 verified loader: 128 rows x 64 fp32 -> fp16 smem pitch AP
// ---------------------------------------------------------------------------
__device__ __forceinline__ void load_conv(__half* sm, const float* __restrict__ g,
                                          int row0, int pitch, int tid) {
#pragma unroll
    for (int it = 0; it < 4; it++) {
        int idx = it * 256 + tid;          // 0..1023
        int row = idx >> 3, q = idx & 7;
        const float* p = g + (size_t)(row0 + row) * pitch + q * 8;
        float4 v0 = *(const float4*)p;
        float4 v1 = *(const float4*)(p + 4);
        __half2 h0 = __halves2half2(__float2half_rn(v0.x), __float2half_rn(v0.y));
        __half2 h1 = __halves2half2(__float2half_rn(v0.z), __float2half_rn(v0.w));
        __half2 h2 = __halves2half2(__float2half_rn(v1.x), __float2half_rn(v1.y));
        __half2 h3 = __halves2half2(__float2half_rn(v1.z), __float2half_rn(v1.w));
        uint4 u;
        u.x = *(unsigned*)&h0; u.y = *(unsigned*)&h1;
        u.z = *(unsigned*)&h2; u.w = *(unsigned*)&h3;
        *(uint4*)(sm + row * AP + q * 8) = u;
    }
}

// ---------------------------------------------------------------------------
// Round-4 verified MMA core: 128x128x64, warp tile 32m x 64n
// ---------------------------------------------------------------------------
__device__ __forceinline__ void mma_core(float acc[2][8][4],
                                         const __half* sA, const __half* sB,
                                         int warp_m, int warp_n, int lane) {
    const int lrow = lane & 15, lkh = (lane >> 4) * 8;
#pragma unroll
    for (int ks = 0; ks < 64; ks += 16) {
        unsigned af[2][4];
#pragma unroll
        for (int mi = 0; mi < 2; mi++)
            ldm4(af[mi], smem_u32(sA + (warp_m * 32 + mi * 16 + lrow) * AP + ks + lkh));
        unsigned bf[8][2];
#pragma unroll
        for (int np = 0; np < 4; np++) {
            unsigned t[4];
            ldm4(t, smem_u32(sB + (warp_n * 64 + np * 16 + lrow) * AP + ks + lkh));
            bf[2*np][0]   = t[0]; bf[2*np+1][0] = t[1];
            bf[2*np][1]   = t[2]; bf[2*np+1][1] = t[3];
        }
#pragma unroll
        for (int mi = 0; mi < 2; mi++)
#pragma unroll
            for (int ni = 0; ni < 8; ni++)
                mma_f16(acc[mi][ni], af[mi], bf[ni]);
    }
}

// ---------------------------------------------------------------------------
// K1 (verbatim round-4): grid(2 dt, BN). z = x @ w1^T, max over 256 m,
// + bias -> g_zmax
// ---------------------------------------------------------------------------
__global__ void __launch_bounds__(256)
k1_mma_max(const float* __restrict__ x, const float* __restrict__ w1,
           const float* __restrict__ b1)
{
    __shared__ __align__(16) __half sA[128 * AP];
    __shared__ __align__(16) __half sB[128 * AP];
    __shared__ float smax[4][128];

    const int tid = threadIdx.x;
    const int lane = tid & 31, w = tid >> 5;
    const int warp_m = w >> 1, warp_n = w & 1;
    const int dt = blockIdx.x, bn = blockIdx.y;

    smax[tid >> 7][tid & 127] = -3.4e38f;
    smax[2 + (tid >> 7)][tid & 127] = -3.4e38f;

    load_conv(sB, w1, dt * 128, CIN, tid);

#pragma unroll
    for (int mt = 0; mt < 2; mt++) {
        __syncthreads();
        load_conv(sA, x, bn * 256 + mt * 128, CIN, tid);
        __syncthreads();

        float acc[2][8][4];
#pragma unroll
        for (int mi = 0; mi < 2; mi++)
#pragma unroll
            for (int ni = 0; ni < 8; ni++)
#pragma unroll
                for (int c = 0; c < 4; c++) acc[mi][ni][c] = 0.f;

        mma_core(acc, sA, sB, warp_m, warp_n, lane);

#pragma unroll
        for (int ni = 0; ni < 8; ni++) {
            float m0 = fmaxf(fmaxf(acc[0][ni][0], acc[0][ni][2]),
                             fmaxf(acc[1][ni][0], acc[1][ni][2]));
            float m1 = fmaxf(fmaxf(acc[0][ni][1], acc[0][ni][3]),
                             fmaxf(acc[1][ni][1], acc[1][ni][3]));
#pragma unroll
            for (int off = 4; off < 32; off <<= 1) {
                m0 = fmaxf(m0, __shfl_xor_sync(0xffffffffu, m0, off));
                m1 = fmaxf(m1, __shfl_xor_sync(0xffffffffu, m1, off));
            }
            if (lane < 4) {
                int col = warp_n * 64 + ni * 8 + lane * 2;
                smax[warp_m][col]     = fmaxf(smax[warp_m][col], m0);
                smax[warp_m][col + 1] = fmaxf(smax[warp_m][col + 1], m1);
            }
        }
    }

    __syncthreads();
    if (tid < 128) {
        float m = fmaxf(fmaxf(smax[0][tid], smax[1][tid]),
                        fmaxf(smax[2][tid], smax[3][tid]));
        g_zmax[(size_t)bn * CMID + dt * 128 + tid] = m + b1[dt * 128 + tid];
    }
}

// ---------------------------------------------------------------------------
// K2 (verbatim round-4): v = zmax @ w2b^T, fp32 SIMT
// ---------------------------------------------------------------------------
__global__ __launch_bounds__(256)
void k2_vgemm(const float* __restrict__ w2)
{
    __shared__ float aT[32 * K2P];
    __shared__ float bT[32 * K2P];

    const int tid = threadIdx.x;
    const int tx = tid & 15, ty = tid >> 4;
    const int o0  = blockIdx.x * 64;
    const int bn0 = blockIdx.y * 64;

    float acc[4][4];
#pragma unroll
    for (int i = 0; i < 4; i++)
#pragma unroll
        for (int j = 0; j < 4; j++) acc[i][j] = 0.f;

    for (int kc = 0; kc < CMID; kc += 32) {
        __syncthreads();
#pragma unroll
        for (int it = 0; it < 8; it++) {
            int l = tid + it * 256;
            int r = l >> 5, k = l & 31;
            aT[k * K2P + r] = g_zmax[(size_t)(bn0 + r) * CMID + kc + k];
            bT[k * K2P + r] = w2[(size_t)(o0 + r) * W2P + CIN + kc + k];
        }
        __syncthreads();
#pragma unroll
        for (int k = 0; k < 32; k++) {
            float a[4], b[4];
#pragma unroll
            for (int i = 0; i < 4; i++) a[i] = aT[k * K2P + ty * 4 + i];
#pragma unroll
            for (int j = 0; j < 4; j++) b[j] = bT[k * K2P + tx * 4 + j];
#pragma unroll
            for (int i = 0; i < 4; i++)
#pragma unroll
                for (int j = 0; j < 4; j++)
                    acc[i][j] = fmaf(a[i], b[j], acc[i][j]);
        }
    }
#pragma unroll
    for (int i = 0; i < 4; i++)
#pragma unroll
        for (int j = 0; j < 4; j++)
            g_v[(size_t)(bn0 + ty * 4 + i) * COUT + o0 + tx * 4 + j] = acc[i][j];
}

// ---------------------------------------------------------------------------
// 4-lane butterfly exchange helper: swaps items across lane^k within the
// (p, p^k) slot pair. it[x][4] = 4 floats per item.
// ---------------------------------------------------------------------------
__device__ __forceinline__ void bfly_pair(float itp[4], float itq[4], int k, bool sw) {
    float t[4], u[4];
#pragma unroll
    for (int j = 0; j < 4; j++) {
        t[j] = __shfl_xor_sync(0xffffffffu, itp[j], k);
        u[j] = __shfl_xor_sync(0xffffffffu, itq[j], k);
    }
#pragma unroll
    for (int j = 0; j < 4; j++) {
        if (sw) itp[j] = u[j];
        else    itq[j] = t[j];
    }
}

// ---------------------------------------------------------------------------
// K3 (round-4 core + shuffle-transposed epilogue): grid(2 nt, BN).
// out = x @ w2a^T + v. After transpose each lane holds 16 contiguous output
// floats of one row -> STG.128 (32 wf per (mi,h) vs 64 for STG.64).
// Values + add order identical to round 4 (bitwise-same output).
// ---------------------------------------------------------------------------
__global__ void __launch_bounds__(256)
k3_mma_out(const float* __restrict__ x, const float* __restrict__ w2,
           float* __restrict__ out)
{
    __shared__ __align__(16) __half sA[128 * AP];
    __shared__ __align__(16) __half sB[128 * AP];
    __shared__ float sv[128];

    const int tid = threadIdx.x;
    const int lane = tid & 31, w = tid >> 5;
    const int warp_m = w >> 1, warp_n = w & 1;
    const int nt = blockIdx.x, bn = blockIdx.y;
    const int c = lane & 3;
    const bool sw1 = (lane & 1), sw2 = (lane & 2);

    if (tid < 128) sv[tid] = g_v[(size_t)bn * COUT + nt * 128 + tid];

    load_conv(sB, w2, nt * 128, W2P, tid);   // w2a = first 64 cols of pitch-320 rows

#pragma unroll
    for (int rt = 0; rt < 2; rt++) {
        const int r0 = bn * 256 + rt * 128;
        __syncthreads();
        load_conv(sA, x, r0, CIN, tid);
        __syncthreads();

        float acc[2][8][4];
#pragma unroll
        for (int mi = 0; mi < 2; mi++)
#pragma unroll
            for (int ni = 0; ni < 8; ni++)
#pragma unroll
                for (int cc = 0; cc < 4; cc++) acc[mi][ni][cc] = 0.f;

        mma_core(acc, sA, sB, warp_m, warp_n, lane);

        // transposed epilogue
#pragma unroll
        for (int mi = 0; mi < 2; mi++) {
#pragma unroll
            for (int h = 0; h < 2; h++) {
                // item p holds (v[2p], v[2p+1]); v[ni] = acc pair + vv (v-add
                // before transpose: indices match round-4 exactly)
                float it[4][4];
#pragma unroll
                for (int ni = 0; ni < 8; ni++) {
                    float2 vv = *(const float2*)(sv + warp_n * 64 + ni * 8 + c * 2);
                    it[ni >> 1][(ni & 1) * 2 + 0] = acc[mi][ni][2 * h + 0] + vv.x;
                    it[ni >> 1][(ni & 1) * 2 + 1] = acc[mi][ni][2 * h + 1] + vv.y;
                }
                // butterfly transpose across the 4 lanes sharing this row:
                // step k=2: pairs (0,2),(1,3); step k=1: pairs (0,1),(2,3)
                bfly_pair(it[0], it[2], 2, sw2);
                bfly_pair(it[1], it[3], 2, sw2);
                bfly_pair(it[0], it[1], 1, sw1);
                bfly_pair(it[2], it[3], 1, sw1);
                // lane (r,c) now holds cols [16c, 16c+16) of its row:
                // F0 = {it0[0],it0[1],it1[0],it1[1]}  (cols 16c+0..3)
                // F1 = {it2[0],it2[1],it3[0],it3[1]}  (cols 16c+4..7)
                // F2 = {it0[2],it0[3],it1[2],it1[3]}  (cols 16c+8..11)
                // F3 = {it2[2],it2[3],it3[2],it3[3]}  (cols 16c+12..15)
                int row = r0 + warp_m * 32 + mi * 16 + h * 8 + (lane >> 2);
                float* orow = out + (size_t)row * COUT + nt * 128 + warp_n * 64 + c * 16;
                float4 F;
                F.x = it[0][0]; F.y = it[0][1]; F.z = it[1][0]; F.w = it[1][1];
                *(float4*)(orow + 0)  = F;
                F.x = it[2][0]; F.y = it[2][1]; F.z = it[3][0]; F.w = it[3][1];
                *(float4*)(orow + 4)  = F;
                F.x = it[0][2]; F.y = it[0][3]; F.z = it[1][2]; F.w = it[1][3];
                *(float4*)(orow + 8)  = F;
                F.x = it[2][2]; F.y = it[2][3]; F.z = it[3][2]; F.w = it[3][3];
                *(float4*)(orow + 12) = F;
            }
        }
    }
}

// ---------------------------------------------------------------------------
extern "C" void kernel_launch(void* const* d_in, const int* in_sizes, int n_in,
                              void* d_out, int out_size) {
    const float* x  = (const float*)d_in[0];   // (8,256,256,64)
    const float* w1 = (const float*)d_in[1];   // (256,64)
    const float* b1 = (const float*)d_in[2];   // (256,)
    const float* w2 = (const float*)d_in[3];   // (256,320)
    float* out = (float*)d_out;                // (8,256,256,256)

    dim3 g1(2, BN_TOT);
    k1_mma_max<<<g1, 256>>>(x, w1, b1);

    dim3 g2(COUT / 64, BN_TOT / 64);
    k2_vgemm<<<g2, 256>>>(w2);

    dim3 g3(2, BN_TOT);
    k3_mma_out<<<g3, 256>>>(x, w2, out);
}